// round 15
// baseline (speedup 1.0000x reference)
#include <cuda_runtime.h>
#include <cuda_fp16.h>
#include <cstdint>
#include <math.h>

#define BATCH 16
#define ZD 256
#define OC 256
#define IC 128
#define FANIN (IC*9)          // 1152
#define NTOT (OC*FANIN)       // 294912
#define HW 64

// ---------------- device scratch (no allocation APIs) ----------------
__device__ float g_dw[BATCH*NTOT];             // delta_w [b][n]
__device__ __half g_wh[BATCH*OC*9*IC];         // weights fp16, [b][oc][tap][cin]

// fp16 mma.sync (sm_80-era PTX — valid on plain compute_103 virtual arch)
__device__ __forceinline__ void mma16816h(float* d, const uint32_t* a,
                                          uint32_t b0, uint32_t b1) {
    asm volatile(
        "mma.sync.aligned.m16n8k16.row.col.f32.f16.f16.f32 "
        "{%0,%1,%2,%3}, {%4,%5,%6,%7}, {%8,%9}, {%0,%1,%2,%3};"
        : "+f"(d[0]), "+f"(d[1]), "+f"(d[2]), "+f"(d[3])
        : "r"(a[0]), "r"(a[1]), "r"(a[2]), "r"(a[3]), "r"(b0), "r"(b1));
}

__device__ __forceinline__ uint32_t pack_h2(float a, float b) {
    __half2 h = __floats2half2_rn(a, b);
    return *reinterpret_cast<uint32_t*>(&h);
}

// k-pair permutation within each 32B (k16) group:
// pair p stored at pos(p) = 2(p&3) | (p>>2); LDS.64 at 8*qc -> (b0,b1).
__device__ __forceinline__ int kperm_pos(int lp) { return ((lp & 3) << 1) | (lp >> 2); }

// ---------------------------------------------------------------------------
// Kernel A: delta[b][n] = sum_k z[b][k] * head_w[n][k]  via HMMA.
// R8 structure (measured optimum). tile_off selects the n-tile range.
// ---------------------------------------------------------------------------
#define HWS_STRIDE 528     // 256 k * 2B + 16B pad

__global__ void __launch_bounds__(256) gemm_hmma(const float* __restrict__ z,
                                                 const float* __restrict__ hw,
                                                 int tile_off)
{
    __shared__ uint4 zf[512];            // A-frags: [kk(16)][lane(32)] x 16B
    __shared__ char  hws[64*HWS_STRIDE]; // B fp16, k-pair permuted

    const int tid = threadIdx.x;
    const int n0  = (blockIdx.x + tile_off) * 64;

    #pragma unroll
    for (int u = 0; u < 2; u++) {
        const int s  = tid + u*256;
        const int kk = s >> 5, l = s & 31;
        const int m  = l >> 2;
        const int kb = kk*16 + 2*(l & 3);
        float2 f0 = *(const float2*)&z[m*ZD + kb];
        float2 f1 = *(const float2*)&z[(m+8)*ZD + kb];
        float2 f2 = *(const float2*)&z[m*ZD + kb + 8];
        float2 f3 = *(const float2*)&z[(m+8)*ZD + kb + 8];
        uint4 v;
        v.x = pack_h2(f0.x, f0.y);
        v.y = pack_h2(f1.x, f1.y);
        v.z = pack_h2(f2.x, f2.y);
        v.w = pack_h2(f3.x, f3.y);
        zf[s] = v;
    }

    #pragma unroll
    for (int half = 0; half < 2; half++) {
        float4 vals[8];
        #pragma unroll
        for (int u = 0; u < 8; u++) {
            const int idx = (half*8 + u)*256 + tid;
            const int row = idx >> 6, kq = idx & 63;
            vals[u] = *(const float4*)&hw[(size_t)(n0 + row)*ZD + kq*4];
        }
        #pragma unroll
        for (int u = 0; u < 8; u++) {
            const int idx = (half*8 + u)*256 + tid;
            const int row = idx >> 6, kq = idx & 63;
            const int g   = kq >> 2;
            const int lp0 = 2*(kq & 3);
            char* rp = hws + row*HWS_STRIDE + g*32;
            *(uint32_t*)(rp + kperm_pos(lp0)*4)     = pack_h2(vals[u].x, vals[u].y);
            *(uint32_t*)(rp + kperm_pos(lp0 + 1)*4) = pack_h2(vals[u].z, vals[u].w);
        }
    }
    __syncthreads();

    const int wid = tid >> 5, lane = tid & 31;
    const int qr = lane >> 2, qc = lane & 3;

    float d[4] = {0.f, 0.f, 0.f, 0.f};
    const char* bp = hws + (wid*8 + qr)*HWS_STRIDE + qc*8;
    #pragma unroll
    for (int kk = 0; kk < 16; kk++) {
        uint4 a = zf[kk*32 + lane];
        uint2 b = *(const uint2*)(bp + kk*32);
        mma16816h(d, (const uint32_t*)&a, b.x, b.y);
    }

    const int n = n0 + wid*8 + 2*qc;
    *(float2*)&g_dw[(size_t)qr*NTOT + n]       = make_float2(d[0], d[1]);
    *(float2*)&g_dw[(size_t)(qr + 8)*NTOT + n] = make_float2(d[2], d[3]);
}

// ---------------------------------------------------------------------------
// Kernel B: standardize + build weights, emit fp16, [b][oc][tap][cin].
// ---------------------------------------------------------------------------
__global__ void __launch_bounds__(128) build_w(const float* __restrict__ base,
                                               int oc_off)
{
    __shared__ __half ws[FANIN];        // [tap][cin]

    const int b  = blockIdx.x >> 7;
    const int oc = (blockIdx.x & 127) + oc_off;
    const int tid = threadIdx.x;

    const float* dwp = &g_dw[(size_t)b*NTOT + oc*FANIN];

    float v[9];
    float s = 0.f, sq = 0.f;
    #pragma unroll
    for (int t = 0; t < 9; t++) {
        v[t] = dwp[tid + t*128];
        s  += v[t];
        sq += v[t]*v[t];
    }
    #pragma unroll
    for (int off = 16; off; off >>= 1) {
        s  += __shfl_xor_sync(0xffffffffu, s,  off);
        sq += __shfl_xor_sync(0xffffffffu, sq, off);
    }
    __shared__ float ss[4], ssq[4];
    const int wid = tid >> 5;
    if ((tid & 31) == 0) { ss[wid] = s; ssq[wid] = sq; }
    __syncthreads();
    s  = ss[0] + ss[1] + ss[2] + ss[3];
    sq = ssq[0] + ssq[1] + ssq[2] + ssq[3];

    const float inv_n = 1.0f / (float)FANIN;
    float mu  = s * inv_n;
    float var = sq * inv_n - mu*mu;
    float rs  = rsqrtf(var + 1e-5f);
    const float inv_sqrt2 = 0.70710678118654752440f;
    float c1 = rs * sqrtf(2.0f / (float)FANIN) * inv_sqrt2;

    const float* bw = &base[(size_t)oc*FANIN];
    #pragma unroll
    for (int t = 0; t < 9; t++) {
        int i = tid + t*128;           // i = cin*9 + tap
        int cin = i / 9, tap = i - cin*9;
        float w = bw[i]*inv_sqrt2 + (v[t] - mu)*c1;
        ws[tap*IC + cin] = __float2half(w);
    }
    __syncthreads();

    uint2* dst = (uint2*)&g_wh[(size_t)(b*OC + oc)*9*IC];
    const uint2* src = (const uint2*)ws;
    #pragma unroll
    for (int i = tid; i < 288; i += 128) dst[i] = src[i];
}

// ---------------------------------------------------------------------------
// Kernel C: implicit-GEMM conv via mma.sync fp16 single-pass, fp32 accum.
// NOW 256 threads / 8 warps, CTA = (2 y-rows, 128 oc, b), 2 CTAs/SM.
// Per-warp work identical to R13 (1 y-row x 64x x 32oc, same MMA order)
// => bit-identical numerics, HMMA ceiling preserved (16 warps/SM).
// Smaller CTAs: finer wave granularity + register slack for gemm co-residency.
// ---------------------------------------------------------------------------
#define XS_STRIDE 144
#define XS_BYTES  (4*66*XS_STRIDE)     // 38016 (2 rows + halo)
#define A_BUF     18432
#define SM_XS     36864                // after 2 A buffers
#define CONV_SMEM (SM_XS + XS_BYTES)   // 74880

__global__ void __launch_bounds__(256, 2) conv_mma(const float* __restrict__ x,
                                                   float* __restrict__ out,
                                                   int oc_off)
{
    extern __shared__ char smem[];
    const int tid  = threadIdx.x;
    const int wid  = tid >> 5;
    const int lane = tid & 31;
    const int y0   = blockIdx.x * 2;
    const int oc0  = blockIdx.y * 128 + oc_off;
    const int b    = blockIdx.z;

    const int mw = wid & 3;       // oc quarter (32)
    const int yl = wid >> 2;      // local y row (0..1)
    const int qr = lane >> 2;
    const int qc = lane & 3;

    float acc[2][8][4];
    #pragma unroll
    for (int mf = 0; mf < 2; mf++)
        #pragma unroll
        for (int nf = 0; nf < 8; nf++)
            #pragma unroll
            for (int q = 0; q < 4; q++) acc[mf][nf][q] = 0.f;

    uint4 nv[4];   // in-flight A tile, 4 chunks per thread (1024 uint4 / 256 thr)

    auto lda = [&](int it) {
        const int ch = it / 9, tap = it - ch*9;
        const size_t abase = ((size_t)((b*OC + oc0)*9 + tap))*IC + (size_t)ch*64;
        #pragma unroll
        for (int u = 0; u < 4; u++) {
            const int i = tid + u*256;
            const int row = i >> 3, j = i & 7;
            const size_t off8 = (abase + (size_t)row*(9*IC)) / 8 + j;
            nv[u] = ((const uint4*)g_wh)[off8];
        }
    };
    auto sta = [&](int buf) {
        char* base = smem + buf*A_BUF;
        #pragma unroll
        for (int u = 0; u < 4; u++) {
            const int i = tid + u*256;
            const int row = i >> 3, j = i & 7;
            *(uint4*)(base + row*XS_STRIDE + j*16) = nv[u];
        }
    };
    auto stage_x = [&](int ch) {
        for (int i = tid; i < 4*32*16; i += 256) {
            const int ys  = i >> 9;              // 0..3
            const int rem = i & 511;
            const int cp  = rem >> 4;            // c-pair 0..31
            const int x4  = rem & 15;
            const int gy  = y0 - 1 + ys;
            if (gy >= 0 && gy < HW) {
                const float4 v0 = *(const float4*)
                    &x[(((size_t)(b*IC + ch*64 + cp*2    ))*HW + gy)*HW + x4*4];
                const float4 v1 = *(const float4*)
                    &x[(((size_t)(b*IC + ch*64 + cp*2 + 1))*HW + gy)*HW + x4*4];
                const float f0[4] = {v0.x, v0.y, v0.z, v0.w};
                const float f1[4] = {v1.x, v1.y, v1.z, v1.w};
                #pragma unroll
                for (int q = 0; q < 4; q++) {
                    __half2 h = __floats2half2_rn(f0[q], f1[q]);
                    *(__half2*)(smem + SM_XS + (ys*66 + x4*4 + q + 1)*XS_STRIDE + cp*4) = h;
                }
            }
        }
    };
    auto compute = [&](int tap, int buf) {
        const int r = tap / 3, s = tap - r*3;
        const char* Ah = smem + buf*A_BUF;
        const int a_row0 = (mw*32 + qr)*XS_STRIDE + qc*4;
        const int bbase  = ((yl + r)*66 + s + qr)*XS_STRIDE + qc*4;
        #pragma unroll
        for (int ks = 0; ks < 4; ks++) {
            const int kb = ks*32;
            uint32_t ah[2][4];
            #pragma unroll
            for (int mf = 0; mf < 2; mf++) {
                const int ar = a_row0 + mf*(16*XS_STRIDE) + kb;
                ah[mf][0] = *(const uint32_t*)(Ah + ar);
                ah[mf][1] = *(const uint32_t*)(Ah + ar + 8*XS_STRIDE);
                ah[mf][2] = *(const uint32_t*)(Ah + ar + 16);
                ah[mf][3] = *(const uint32_t*)(Ah + ar + 8*XS_STRIDE + 16);
            }
            #pragma unroll
            for (int nf = 0; nf < 8; nf++) {
                const int ba = bbase + nf*(8*XS_STRIDE) + kb;
                const uint32_t b0 = *(const uint32_t*)(smem + SM_XS + ba);
                const uint32_t b1 = *(const uint32_t*)(smem + SM_XS + ba + 16);
                #pragma unroll
                for (int mf = 0; mf < 2; mf++)
                    mma16816h(acc[mf][nf], ah[mf], b0, b1);
            }
        }
    };

    for (int i = tid; i < XS_BYTES/16; i += 256)
        *(uint4*)(smem + SM_XS + i*16) = make_uint4(0u,0u,0u,0u);
    __syncthreads();
    stage_x(0);
    lda(0); sta(0);
    __syncthreads();

    for (int it = 0; it < 18; it++) {
        const int tap = (it < 9) ? it : it - 9;
        const int buf = it & 1;
        if (it < 17) lda(it + 1);
        compute(tap, buf);
        if (it == 8) {
            __syncthreads();
            stage_x(1);
            sta(buf ^ 1);
            __syncthreads();
        } else if (it < 17) {
            sta(buf ^ 1);
            __syncthreads();
        }
    }

    const int y = y0 + yl;
    #pragma unroll
    for (int mf = 0; mf < 2; mf++) {
        const int oc = oc0 + mw*32 + mf*16 + qr;
        float* op0 = out + (((size_t)(b*OC + oc    )*HW) + y)*HW;
        float* op1 = out + (((size_t)(b*OC + oc + 8)*HW) + y)*HW;
        #pragma unroll
        for (int nf = 0; nf < 8; nf++) {
            const int xp = nf*8 + qc*2;
            *(float2*)&op0[xp] = make_float2(acc[mf][nf][0], acc[mf][nf][1]);
            *(float2*)&op1[xp] = make_float2(acc[mf][nf][2], acc[mf][nf][3]);
        }
    }
}

// ---------------------------------------------------------------------------
// Launcher: oc-half pipelined across 2 streams. With 2-CTA/SM conv, SMs
// draining conv CTAs can host gemm CTAs (32K + 16K regs) -> real overlap.
// Sequential fallback if stream/event creation fails.
// ---------------------------------------------------------------------------
extern "C" void kernel_launch(void* const* d_in, const int* in_sizes, int n_in,
                              void* d_out, int out_size)
{
    const float* x    = (const float*)d_in[0];  // [16,128,64,64]
    const float* z    = (const float*)d_in[1];  // [16,256]
    const float* bw   = (const float*)d_in[2];  // [256,128,3,3]
    const float* hw   = (const float*)d_in[3];  // [294912,256]
    float*       out  = (float*)d_out;          // [16,256,64,64]

    static bool init_done = false;
    static bool two_streams = false;
    static cudaStream_t s2 = 0;
    static cudaEvent_t evA = 0, evB = 0;
    if (!init_done) {
        cudaFuncSetAttribute(conv_mma, cudaFuncAttributeMaxDynamicSharedMemorySize, CONV_SMEM);
        two_streams =
            (cudaStreamCreateWithFlags(&s2, cudaStreamNonBlocking) == cudaSuccess) &&
            (cudaEventCreateWithFlags(&evA, cudaEventDisableTiming) == cudaSuccess) &&
            (cudaEventCreateWithFlags(&evB, cudaEventDisableTiming) == cudaSuccess);
        init_done = true;
    }

    if (two_streams) {
        gemm_hmma<<<2304, 256>>>(z, hw, 0);
        build_w<<<BATCH*128, 128>>>(bw, 0);
        cudaEventRecord(evA, 0);
        cudaStreamWaitEvent(s2, evA, 0);
        conv_mma<<<dim3(32, 1, BATCH), 256, CONV_SMEM, s2>>>(x, out, 0);
        gemm_hmma<<<2304, 256>>>(z, hw, 2304);
        build_w<<<BATCH*128, 128>>>(bw, 128);
        conv_mma<<<dim3(32, 1, BATCH), 256, CONV_SMEM>>>(x, out, 128);
        cudaEventRecord(evB, s2);
        cudaStreamWaitEvent(0, evB, 0);
    } else {
        gemm_hmma<<<NTOT/64, 256>>>(z, hw, 0);
        build_w<<<BATCH*128, 128>>>(bw, 0);
        build_w<<<BATCH*128, 128>>>(bw, 128);
        conv_mma<<<dim3(32, 2, BATCH), 256, CONV_SMEM>>>(x, out, 0);
    }
}

// round 16
// speedup vs baseline: 1.0238x; 1.0238x over previous
#include <cuda_runtime.h>
#include <cuda_fp16.h>
#include <cstdint>
#include <math.h>

#define BATCH 16
#define ZD 256
#define OC 256
#define IC 128
#define FANIN (IC*9)          // 1152
#define NTOT (OC*FANIN)       // 294912
#define HW 64

// ---------------- device scratch (no allocation APIs) ----------------
__device__ float g_dw[BATCH*NTOT];             // delta_w [b][n]
__device__ __half g_wh[BATCH*OC*9*IC];         // weights fp16, [b][oc][tap][cin]

// fp16 mma.sync (sm_80-era PTX — valid on plain compute_103 virtual arch)
__device__ __forceinline__ void mma16816h(float* d, const uint32_t* a,
                                          uint32_t b0, uint32_t b1) {
    asm volatile(
        "mma.sync.aligned.m16n8k16.row.col.f32.f16.f16.f32 "
        "{%0,%1,%2,%3}, {%4,%5,%6,%7}, {%8,%9}, {%0,%1,%2,%3};"
        : "+f"(d[0]), "+f"(d[1]), "+f"(d[2]), "+f"(d[3])
        : "r"(a[0]), "r"(a[1]), "r"(a[2]), "r"(a[3]), "r"(b0), "r"(b1));
}

__device__ __forceinline__ uint32_t pack_h2(float a, float b) {
    __half2 h = __floats2half2_rn(a, b);
    return *reinterpret_cast<uint32_t*>(&h);
}

__device__ __forceinline__ uint32_t smem_u32(const void* p) {
    return (uint32_t)__cvta_generic_to_shared(p);
}

// ---------------------------------------------------------------------------
// Kernel A: delta[b][n] = sum_k z[b][k] * head_w[n][k]  via HMMA.
// cp.async.cg staging: head_w streams gmem->L2->smem BYPASSING L1 (the
// measured compound bind). B kept fp32 in smem; fp16 conversion done per
// fragment in the compute loop (identical rounding/order -> bit-identical).
// Block: 64-n tile, 256 threads = 8 warps, warp = one n8 strip over K=256.
// ---------------------------------------------------------------------------
#define BROW 1056                      // 256 fp32 (1024B) + 32B pad (banks: 264%32=8)
#define GEMM_ZF_BYTES 8192
#define GEMM_SMEM (GEMM_ZF_BYTES + 64*BROW)   // 8192 + 67584 = 75776

__global__ void __launch_bounds__(256) gemm_hmma(const float* __restrict__ z,
                                                 const float* __restrict__ hw)
{
    extern __shared__ char smem[];
    uint4* zf = (uint4*)smem;                       // A-frags: [kk(16)][lane(32)]
    char*  bs = smem + GEMM_ZF_BYTES;               // B fp32 tile [64 rows][BROW]

    const int tid = threadIdx.x;
    const int n0  = blockIdx.x * 64;

    // ---- issue cp.async.cg for the whole 64x256 fp32 tile (L1-bypass) ----
    {
        const char* gsrc = (const char*)(hw + (size_t)n0*ZD);
        const uint32_t bsa = smem_u32(bs);
        #pragma unroll
        for (int u = 0; u < 16; u++) {
            const int idx  = u*256 + tid;
            const int row  = idx >> 6, chunk = idx & 63;
            const uint32_t dst = bsa + row*BROW + chunk*16;
            const char*    src = gsrc + (size_t)row*1024 + chunk*16;
            asm volatile("cp.async.cg.shared.global [%0], [%1], 16;"
                         :: "r"(dst), "l"(src));
        }
        asm volatile("cp.async.commit_group;");
    }

    // ---- build z A-fragments while the async copies are in flight ----
    #pragma unroll
    for (int u = 0; u < 2; u++) {
        const int s  = tid + u*256;
        const int kk = s >> 5, l = s & 31;
        const int m  = l >> 2;
        const int kb = kk*16 + 2*(l & 3);
        float2 f0 = *(const float2*)&z[m*ZD + kb];
        float2 f1 = *(const float2*)&z[(m+8)*ZD + kb];
        float2 f2 = *(const float2*)&z[m*ZD + kb + 8];
        float2 f3 = *(const float2*)&z[(m+8)*ZD + kb + 8];
        uint4 v;
        v.x = pack_h2(f0.x, f0.y);
        v.y = pack_h2(f1.x, f1.y);
        v.z = pack_h2(f2.x, f2.y);
        v.w = pack_h2(f3.x, f3.y);
        zf[s] = v;
    }

    asm volatile("cp.async.wait_group 0;");
    __syncthreads();

    // ---- compute: warp w -> n rows w*8..w*8+7, K=256 (16 kk steps) ----
    const int wid = tid >> 5, lane = tid & 31;
    const int qr = lane >> 2, qc = lane & 3;

    float d[4] = {0.f, 0.f, 0.f, 0.f};
    const char* bp = bs + (wid*8 + qr)*BROW + qc*8;   // fp32: k = 2qc
    #pragma unroll
    for (int kk = 0; kk < 16; kk++) {
        uint4 a = zf[kk*32 + lane];
        const float2 f0 = *(const float2*)(bp + kk*64);        // k = 2qc, 2qc+1
        const float2 f1 = *(const float2*)(bp + kk*64 + 32);   // k = 2qc+8, 2qc+9
        mma16816h(d, (const uint32_t*)&a,
                  pack_h2(f0.x, f0.y), pack_h2(f1.x, f1.y));
    }

    const int n = n0 + wid*8 + 2*qc;
    *(float2*)&g_dw[(size_t)qr*NTOT + n]       = make_float2(d[0], d[1]);
    *(float2*)&g_dw[(size_t)(qr + 8)*NTOT + n] = make_float2(d[2], d[3]);
}

// ---------------------------------------------------------------------------
// Kernel B: standardize + build weights, emit fp16, [b][oc][tap][cin].
// Transpose via smem so global writes are coalesced 8B stores.
// ---------------------------------------------------------------------------
__global__ void __launch_bounds__(128) build_w(const float* __restrict__ base)
{
    __shared__ __half ws[FANIN];        // [tap][cin]

    const int b  = blockIdx.x >> 8;
    const int oc = blockIdx.x & 255;
    const int tid = threadIdx.x;

    const float* dwp = &g_dw[(size_t)b*NTOT + oc*FANIN];

    float v[9];
    float s = 0.f, sq = 0.f;
    #pragma unroll
    for (int t = 0; t < 9; t++) {
        v[t] = dwp[tid + t*128];
        s  += v[t];
        sq += v[t]*v[t];
    }
    #pragma unroll
    for (int off = 16; off; off >>= 1) {
        s  += __shfl_xor_sync(0xffffffffu, s,  off);
        sq += __shfl_xor_sync(0xffffffffu, sq, off);
    }
    __shared__ float ss[4], ssq[4];
    const int wid = tid >> 5;
    if ((tid & 31) == 0) { ss[wid] = s; ssq[wid] = sq; }
    __syncthreads();
    s  = ss[0] + ss[1] + ss[2] + ss[3];
    sq = ssq[0] + ssq[1] + ssq[2] + ssq[3];

    const float inv_n = 1.0f / (float)FANIN;
    float mu  = s * inv_n;
    float var = sq * inv_n - mu*mu;
    float rs  = rsqrtf(var + 1e-5f);
    const float inv_sqrt2 = 0.70710678118654752440f;
    float c1 = rs * sqrtf(2.0f / (float)FANIN) * inv_sqrt2;

    const float* bw = &base[(size_t)oc*FANIN];
    #pragma unroll
    for (int t = 0; t < 9; t++) {
        int i = tid + t*128;           // i = cin*9 + tap
        int cin = i / 9, tap = i - cin*9;
        float w = bw[i]*inv_sqrt2 + (v[t] - mu)*c1;
        ws[tap*IC + cin] = __float2half(w);
    }
    __syncthreads();

    // coalesced flush: 1152 halves = 288 x 8B
    uint2* dst = (uint2*)&g_wh[(size_t)(b*OC + oc)*9*IC];
    const uint2* src = (const uint2*)ws;
    #pragma unroll
    for (int i = tid; i < 288; i += 128) dst[i] = src[i];
}

// ---------------------------------------------------------------------------
// Kernel C: implicit-GEMM conv via mma.sync fp16 single-pass, fp32 accum.
// CTA = (4 y-rows, 128-oc tile, b). 512 threads = 16 warps, warp tile 32oc x 64n.
// R13 layout — at the 512 MAC/cyc/SM HMMA ceiling, do not touch.
// ---------------------------------------------------------------------------
#define XS_STRIDE 144
#define XS_BYTES  (6*66*XS_STRIDE)     // 57024
#define A_BUF     18432
#define SM_XS     36864
#define CONV_SMEM (SM_XS + XS_BYTES)   // 93888

__global__ void __launch_bounds__(512, 1) conv_mma(const float* __restrict__ x,
                                                   float* __restrict__ out)
{
    extern __shared__ char smem[];
    const int tid  = threadIdx.x;
    const int wid  = tid >> 5;
    const int lane = tid & 31;
    const int y0   = blockIdx.x * 4;
    const int oc0  = blockIdx.y * 128;
    const int b    = blockIdx.z;

    const int mw = wid & 3;
    const int yl = wid >> 2;
    const int qr = lane >> 2;
    const int qc = lane & 3;

    float acc[2][8][4];
    #pragma unroll
    for (int mf = 0; mf < 2; mf++)
        #pragma unroll
        for (int nf = 0; nf < 8; nf++)
            #pragma unroll
            for (int q = 0; q < 4; q++) acc[mf][nf][q] = 0.f;

    uint4 nv[2];

    auto lda = [&](int it) {
        const int ch = it / 9, tap = it - ch*9;
        const size_t abase = ((size_t)((b*OC + oc0)*9 + tap))*IC + (size_t)ch*64;
        #pragma unroll
        for (int u = 0; u < 2; u++) {
            const int i = tid + u*512;
            const int row = i >> 3, j = i & 7;
            const size_t off8 = (abase + (size_t)row*(9*IC)) / 8 + j;
            nv[u] = ((const uint4*)g_wh)[off8];
        }
    };
    auto sta = [&](int buf) {
        char* base = smem + buf*A_BUF;
        #pragma unroll
        for (int u = 0; u < 2; u++) {
            const int i = tid + u*512;
            const int row = i >> 3, j = i & 7;
            *(uint4*)(base + row*XS_STRIDE + j*16) = nv[u];
        }
    };
    auto stage_x = [&](int ch) {
        for (int i = tid; i < 6*32*16; i += 512) {
            const int ys  = i >> 9;
            const int rem = i & 511;
            const int cp  = rem >> 4;
            const int x4  = rem & 15;
            const int gy  = y0 - 1 + ys;
            if (gy >= 0 && gy < HW) {
                const float4 v0 = *(const float4*)
                    &x[(((size_t)(b*IC + ch*64 + cp*2    ))*HW + gy)*HW + x4*4];
                const float4 v1 = *(const float4*)
                    &x[(((size_t)(b*IC + ch*64 + cp*2 + 1))*HW + gy)*HW + x4*4];
                const float f0[4] = {v0.x, v0.y, v0.z, v0.w};
                const float f1[4] = {v1.x, v1.y, v1.z, v1.w};
                #pragma unroll
                for (int q = 0; q < 4; q++) {
                    __half2 h = __floats2half2_rn(f0[q], f1[q]);
                    *(__half2*)(smem + SM_XS + (ys*66 + x4*4 + q + 1)*XS_STRIDE + cp*4) = h;
                }
            }
        }
    };
    auto compute = [&](int tap, int buf) {
        const int r = tap / 3, s = tap - r*3;
        const char* Ah = smem + buf*A_BUF;
        const int a_row0 = (mw*32 + qr)*XS_STRIDE + qc*4;
        const int bbase  = ((yl + r)*66 + s + qr)*XS_STRIDE + qc*4;
        #pragma unroll
        for (int ks = 0; ks < 4; ks++) {
            const int kb = ks*32;
            uint32_t ah[2][4];
            #pragma unroll
            for (int mf = 0; mf < 2; mf++) {
                const int ar = a_row0 + mf*(16*XS_STRIDE) + kb;
                ah[mf][0] = *(const uint32_t*)(Ah + ar);
                ah[mf][1] = *(const uint32_t*)(Ah + ar + 8*XS_STRIDE);
                ah[mf][2] = *(const uint32_t*)(Ah + ar + 16);
                ah[mf][3] = *(const uint32_t*)(Ah + ar + 8*XS_STRIDE + 16);
            }
            #pragma unroll
            for (int nf = 0; nf < 8; nf++) {
                const int ba = bbase + nf*(8*XS_STRIDE) + kb;
                const uint32_t b0 = *(const uint32_t*)(smem + SM_XS + ba);
                const uint32_t b1 = *(const uint32_t*)(smem + SM_XS + ba + 16);
                #pragma unroll
                for (int mf = 0; mf < 2; mf++)
                    mma16816h(acc[mf][nf], ah[mf], b0, b1);
            }
        }
    };

    for (int i = tid; i < XS_BYTES/16; i += 512)
        *(uint4*)(smem + SM_XS + i*16) = make_uint4(0u,0u,0u,0u);
    __syncthreads();
    stage_x(0);
    lda(0); sta(0);
    __syncthreads();

    for (int it = 0; it < 18; it++) {
        const int tap = (it < 9) ? it : it - 9;
        const int buf = it & 1;
        if (it < 17) lda(it + 1);
        compute(tap, buf);
        if (it == 8) {
            __syncthreads();
            stage_x(1);
            sta(buf ^ 1);
            __syncthreads();
        } else if (it < 17) {
            sta(buf ^ 1);
            __syncthreads();
        }
    }

    const int y = y0 + yl;
    #pragma unroll
    for (int mf = 0; mf < 2; mf++) {
        const int oc = oc0 + mw*32 + mf*16 + qr;
        float* op0 = out + (((size_t)(b*OC + oc    )*HW) + y)*HW;
        float* op1 = out + (((size_t)(b*OC + oc + 8)*HW) + y)*HW;
        #pragma unroll
        for (int nf = 0; nf < 8; nf++) {
            const int xp = nf*8 + qc*2;
            *(float2*)&op0[xp] = make_float2(acc[mf][nf][0], acc[mf][nf][1]);
            *(float2*)&op1[xp] = make_float2(acc[mf][nf][2], acc[mf][nf][3]);
        }
    }
}

// ---------------------------------------------------------------------------
extern "C" void kernel_launch(void* const* d_in, const int* in_sizes, int n_in,
                              void* d_out, int out_size)
{
    const float* x    = (const float*)d_in[0];  // [16,128,64,64]
    const float* z    = (const float*)d_in[1];  // [16,256]
    const float* bw   = (const float*)d_in[2];  // [256,128,3,3]
    const float* hw   = (const float*)d_in[3];  // [294912,256]
    float*       out  = (float*)d_out;          // [16,256,64,64]

    static bool attr_set = false;
    if (!attr_set) {
        cudaFuncSetAttribute(conv_mma,  cudaFuncAttributeMaxDynamicSharedMemorySize, CONV_SMEM);
        cudaFuncSetAttribute(gemm_hmma, cudaFuncAttributeMaxDynamicSharedMemorySize, GEMM_SMEM);
        attr_set = true;
    }

    gemm_hmma<<<NTOT/64, 256, GEMM_SMEM>>>(z, hw);
    build_w<<<BATCH*OC, 128>>>(bw);
    conv_mma<<<dim3(16, 2, BATCH), 512, CONV_SMEM>>>(x, out);
}

// round 17
// speedup vs baseline: 1.0303x; 1.0064x over previous
#include <cuda_runtime.h>
#include <cuda_fp16.h>
#include <cstdint>
#include <math.h>

#define BATCH 16
#define ZD 256
#define OC 256
#define IC 128
#define FANIN (IC*9)          // 1152
#define NTOT (OC*FANIN)       // 294912
#define HW 64

// ---------------- device scratch (no allocation APIs) ----------------
__device__ float g_dw[BATCH*NTOT];             // delta_w [b][n]
__device__ __half g_wh[BATCH*OC*9*IC];         // weights fp16, [b][oc][tap][cin]

// fp16 mma.sync (sm_80-era PTX — valid on plain compute_103 virtual arch)
__device__ __forceinline__ void mma16816h(float* d, const uint32_t* a,
                                          uint32_t b0, uint32_t b1) {
    asm volatile(
        "mma.sync.aligned.m16n8k16.row.col.f32.f16.f16.f32 "
        "{%0,%1,%2,%3}, {%4,%5,%6,%7}, {%8,%9}, {%0,%1,%2,%3};"
        : "+f"(d[0]), "+f"(d[1]), "+f"(d[2]), "+f"(d[3])
        : "r"(a[0]), "r"(a[1]), "r"(a[2]), "r"(a[3]), "r"(b0), "r"(b1));
}

__device__ __forceinline__ uint32_t pack_h2(float a, float b) {
    __half2 h = __floats2half2_rn(a, b);
    return *reinterpret_cast<uint32_t*>(&h);
}

__device__ __forceinline__ uint32_t smem_u32(const void* p) {
    return (uint32_t)__cvta_generic_to_shared(p);
}

// ---------------------------------------------------------------------------
// Kernel A: delta[b][n] = sum_k z[b][k] * head_w[n][k]  via HMMA.
// cp.async.cg (L1-bypass) staging in TWO commit groups (K-halves): the
// second half's arrival hides under the first half's MMA compute.
// Block: 64-n tile, 256 threads = 8 warps, warp = one n8 strip over K=256.
// ---------------------------------------------------------------------------
#define BROW 1056                      // 256 fp32 (1024B) + 32B pad (banks: 264%32=8)
#define GEMM_ZF_BYTES 8192
#define GEMM_SMEM (GEMM_ZF_BYTES + 64*BROW)   // 75776

__global__ void __launch_bounds__(256) gemm_hmma(const float* __restrict__ z,
                                                 const float* __restrict__ hw)
{
    extern __shared__ char smem[];
    uint4* zf = (uint4*)smem;                       // A-frags: [kk(16)][lane(32)]
    char*  bs = smem + GEMM_ZF_BYTES;               // B fp32 tile [64 rows][BROW]

    const int tid = threadIdx.x;
    const int n0  = blockIdx.x * 64;

    const char* gsrc = (const char*)(hw + (size_t)n0*ZD);
    const uint32_t bsa = smem_u32(bs);

    // ---- group A: k chunks 0..31 (k = 0..127) for all 64 rows ----
    #pragma unroll
    for (int u = 0; u < 8; u++) {
        const int idx  = u*256 + tid;               // 0..2047
        const int row  = idx >> 5, chunk = idx & 31;
        asm volatile("cp.async.cg.shared.global [%0], [%1], 16;"
                     :: "r"(bsa + row*BROW + chunk*16),
                        "l"(gsrc + (size_t)row*1024 + chunk*16));
    }
    asm volatile("cp.async.commit_group;");

    // ---- group B: k chunks 32..63 (k = 128..255) ----
    #pragma unroll
    for (int u = 0; u < 8; u++) {
        const int idx  = u*256 + tid;
        const int row  = idx >> 5, chunk = (idx & 31) + 32;
        asm volatile("cp.async.cg.shared.global [%0], [%1], 16;"
                     :: "r"(bsa + row*BROW + chunk*16),
                        "l"(gsrc + (size_t)row*1024 + chunk*16));
    }
    asm volatile("cp.async.commit_group;");

    // ---- build z A-fragments while copies are in flight ----
    #pragma unroll
    for (int u = 0; u < 2; u++) {
        const int s  = tid + u*256;
        const int kk = s >> 5, l = s & 31;
        const int m  = l >> 2;
        const int kb = kk*16 + 2*(l & 3);
        float2 f0 = *(const float2*)&z[m*ZD + kb];
        float2 f1 = *(const float2*)&z[(m+8)*ZD + kb];
        float2 f2 = *(const float2*)&z[m*ZD + kb + 8];
        float2 f3 = *(const float2*)&z[(m+8)*ZD + kb + 8];
        uint4 v;
        v.x = pack_h2(f0.x, f0.y);
        v.y = pack_h2(f1.x, f1.y);
        v.z = pack_h2(f2.x, f2.y);
        v.w = pack_h2(f3.x, f3.y);
        zf[s] = v;
    }

    const int wid = tid >> 5, lane = tid & 31;
    const int qr = lane >> 2, qc = lane & 3;
    const char* bp = bs + (wid*8 + qr)*BROW + qc*8;

    float d[4] = {0.f, 0.f, 0.f, 0.f};

    // ---- half 0: wait group A only (B still in flight) ----
    asm volatile("cp.async.wait_group 1;");
    __syncthreads();
    #pragma unroll
    for (int kk = 0; kk < 8; kk++) {
        uint4 a = zf[kk*32 + lane];
        const float2 f0 = *(const float2*)(bp + kk*64);
        const float2 f1 = *(const float2*)(bp + kk*64 + 32);
        mma16816h(d, (const uint32_t*)&a,
                  pack_h2(f0.x, f0.y), pack_h2(f1.x, f1.y));
    }

    // ---- half 1 ----
    asm volatile("cp.async.wait_group 0;");
    __syncthreads();
    #pragma unroll
    for (int kk = 8; kk < 16; kk++) {
        uint4 a = zf[kk*32 + lane];
        const float2 f0 = *(const float2*)(bp + kk*64);
        const float2 f1 = *(const float2*)(bp + kk*64 + 32);
        mma16816h(d, (const uint32_t*)&a,
                  pack_h2(f0.x, f0.y), pack_h2(f1.x, f1.y));
    }

    const int n = n0 + wid*8 + 2*qc;
    *(float2*)&g_dw[(size_t)qr*NTOT + n]       = make_float2(d[0], d[1]);
    *(float2*)&g_dw[(size_t)(qr + 8)*NTOT + n] = make_float2(d[2], d[3]);
}

// ---------------------------------------------------------------------------
// Kernel B: standardize + build weights, emit fp16, [b][oc][tap][cin].
// ---------------------------------------------------------------------------
__global__ void __launch_bounds__(128) build_w(const float* __restrict__ base)
{
    __shared__ __half ws[FANIN];        // [tap][cin]

    const int b  = blockIdx.x >> 8;
    const int oc = blockIdx.x & 255;
    const int tid = threadIdx.x;

    const float* dwp = &g_dw[(size_t)b*NTOT + oc*FANIN];

    float v[9];
    float s = 0.f, sq = 0.f;
    #pragma unroll
    for (int t = 0; t < 9; t++) {
        v[t] = dwp[tid + t*128];
        s  += v[t];
        sq += v[t]*v[t];
    }
    #pragma unroll
    for (int off = 16; off; off >>= 1) {
        s  += __shfl_xor_sync(0xffffffffu, s,  off);
        sq += __shfl_xor_sync(0xffffffffu, sq, off);
    }
    __shared__ float ss[4], ssq[4];
    const int wid = tid >> 5;
    if ((tid & 31) == 0) { ss[wid] = s; ssq[wid] = sq; }
    __syncthreads();
    s  = ss[0] + ss[1] + ss[2] + ss[3];
    sq = ssq[0] + ssq[1] + ssq[2] + ssq[3];

    const float inv_n = 1.0f / (float)FANIN;
    float mu  = s * inv_n;
    float var = sq * inv_n - mu*mu;
    float rs  = rsqrtf(var + 1e-5f);
    const float inv_sqrt2 = 0.70710678118654752440f;
    float c1 = rs * sqrtf(2.0f / (float)FANIN) * inv_sqrt2;

    const float* bw = &base[(size_t)oc*FANIN];
    #pragma unroll
    for (int t = 0; t < 9; t++) {
        int i = tid + t*128;           // i = cin*9 + tap
        int cin = i / 9, tap = i - cin*9;
        float w = bw[i]*inv_sqrt2 + (v[t] - mu)*c1;
        ws[tap*IC + cin] = __float2half(w);
    }
    __syncthreads();

    uint2* dst = (uint2*)&g_wh[(size_t)(b*OC + oc)*9*IC];
    const uint2* src = (const uint2*)ws;
    #pragma unroll
    for (int i = tid; i < 288; i += 128) dst[i] = src[i];
}

// ---------------------------------------------------------------------------
// Kernel C: implicit-GEMM conv via mma.sync fp16 single-pass, fp32 accum.
// CTA = (4 y-rows, 128-oc tile, b). 512 threads = 16 warps, warp tile 32oc x 64n.
// R13 layout — at the 512 MAC/cyc/SM HMMA ceiling, do not touch.
// ---------------------------------------------------------------------------
#define XS_STRIDE 144
#define XS_BYTES  (6*66*XS_STRIDE)     // 57024
#define A_BUF     18432
#define SM_XS     36864
#define CONV_SMEM (SM_XS + XS_BYTES)   // 93888

__global__ void __launch_bounds__(512, 1) conv_mma(const float* __restrict__ x,
                                                   float* __restrict__ out)
{
    extern __shared__ char smem[];
    const int tid  = threadIdx.x;
    const int wid  = tid >> 5;
    const int lane = tid & 31;
    const int y0   = blockIdx.x * 4;
    const int oc0  = blockIdx.y * 128;
    const int b    = blockIdx.z;

    const int mw = wid & 3;
    const int yl = wid >> 2;
    const int qr = lane >> 2;
    const int qc = lane & 3;

    float acc[2][8][4];
    #pragma unroll
    for (int mf = 0; mf < 2; mf++)
        #pragma unroll
        for (int nf = 0; nf < 8; nf++)
            #pragma unroll
            for (int q = 0; q < 4; q++) acc[mf][nf][q] = 0.f;

    uint4 nv[2];

    auto lda = [&](int it) {
        const int ch = it / 9, tap = it - ch*9;
        const size_t abase = ((size_t)((b*OC + oc0)*9 + tap))*IC + (size_t)ch*64;
        #pragma unroll
        for (int u = 0; u < 2; u++) {
            const int i = tid + u*512;
            const int row = i >> 3, j = i & 7;
            const size_t off8 = (abase + (size_t)row*(9*IC)) / 8 + j;
            nv[u] = ((const uint4*)g_wh)[off8];
        }
    };
    auto sta = [&](int buf) {
        char* base = smem + buf*A_BUF;
        #pragma unroll
        for (int u = 0; u < 2; u++) {
            const int i = tid + u*512;
            const int row = i >> 3, j = i & 7;
            *(uint4*)(base + row*XS_STRIDE + j*16) = nv[u];
        }
    };
    auto stage_x = [&](int ch) {
        for (int i = tid; i < 6*32*16; i += 512) {
            const int ys  = i >> 9;
            const int rem = i & 511;
            const int cp  = rem >> 4;
            const int x4  = rem & 15;
            const int gy  = y0 - 1 + ys;
            if (gy >= 0 && gy < HW) {
                const float4 v0 = *(const float4*)
                    &x[(((size_t)(b*IC + ch*64 + cp*2    ))*HW + gy)*HW + x4*4];
                const float4 v1 = *(const float4*)
                    &x[(((size_t)(b*IC + ch*64 + cp*2 + 1))*HW + gy)*HW + x4*4];
                const float f0[4] = {v0.x, v0.y, v0.z, v0.w};
                const float f1[4] = {v1.x, v1.y, v1.z, v1.w};
                #pragma unroll
                for (int q = 0; q < 4; q++) {
                    __half2 h = __floats2half2_rn(f0[q], f1[q]);
                    *(__half2*)(smem + SM_XS + (ys*66 + x4*4 + q + 1)*XS_STRIDE + cp*4) = h;
                }
            }
        }
    };
    auto compute = [&](int tap, int buf) {
        const int r = tap / 3, s = tap - r*3;
        const char* Ah = smem + buf*A_BUF;
        const int a_row0 = (mw*32 + qr)*XS_STRIDE + qc*4;
        const int bbase  = ((yl + r)*66 + s + qr)*XS_STRIDE + qc*4;
        #pragma unroll
        for (int ks = 0; ks < 4; ks++) {
            const int kb = ks*32;
            uint32_t ah[2][4];
            #pragma unroll
            for (int mf = 0; mf < 2; mf++) {
                const int ar = a_row0 + mf*(16*XS_STRIDE) + kb;
                ah[mf][0] = *(const uint32_t*)(Ah + ar);
                ah[mf][1] = *(const uint32_t*)(Ah + ar + 8*XS_STRIDE);
                ah[mf][2] = *(const uint32_t*)(Ah + ar + 16);
                ah[mf][3] = *(const uint32_t*)(Ah + ar + 8*XS_STRIDE + 16);
            }
            #pragma unroll
            for (int nf = 0; nf < 8; nf++) {
                const int ba = bbase + nf*(8*XS_STRIDE) + kb;
                const uint32_t b0 = *(const uint32_t*)(smem + SM_XS + ba);
                const uint32_t b1 = *(const uint32_t*)(smem + SM_XS + ba + 16);
                #pragma unroll
                for (int mf = 0; mf < 2; mf++)
                    mma16816h(acc[mf][nf], ah[mf], b0, b1);
            }
        }
    };

    for (int i = tid; i < XS_BYTES/16; i += 512)
        *(uint4*)(smem + SM_XS + i*16) = make_uint4(0u,0u,0u,0u);
    __syncthreads();
    stage_x(0);
    lda(0); sta(0);
    __syncthreads();

    for (int it = 0; it < 18; it++) {
        const int tap = (it < 9) ? it : it - 9;
        const int buf = it & 1;
        if (it < 17) lda(it + 1);
        compute(tap, buf);
        if (it == 8) {
            __syncthreads();
            stage_x(1);
            sta(buf ^ 1);
            __syncthreads();
        } else if (it < 17) {
            sta(buf ^ 1);
            __syncthreads();
        }
    }

    const int y = y0 + yl;
    #pragma unroll
    for (int mf = 0; mf < 2; mf++) {
        const int oc = oc0 + mw*32 + mf*16 + qr;
        float* op0 = out + (((size_t)(b*OC + oc    )*HW) + y)*HW;
        float* op1 = out + (((size_t)(b*OC + oc + 8)*HW) + y)*HW;
        #pragma unroll
        for (int nf = 0; nf < 8; nf++) {
            const int xp = nf*8 + qc*2;
            *(float2*)&op0[xp] = make_float2(acc[mf][nf][0], acc[mf][nf][1]);
            *(float2*)&op1[xp] = make_float2(acc[mf][nf][2], acc[mf][nf][3]);
        }
    }
}

// ---------------------------------------------------------------------------
extern "C" void kernel_launch(void* const* d_in, const int* in_sizes, int n_in,
                              void* d_out, int out_size)
{
    const float* x    = (const float*)d_in[0];  // [16,128,64,64]
    const float* z    = (const float*)d_in[1];  // [16,256]
    const float* bw   = (const float*)d_in[2];  // [256,128,3,3]
    const float* hw   = (const float*)d_in[3];  // [294912,256]
    float*       out  = (float*)d_out;          // [16,256,64,64]

    static bool attr_set = false;
    if (!attr_set) {
        cudaFuncSetAttribute(conv_mma,  cudaFuncAttributeMaxDynamicSharedMemorySize, CONV_SMEM);
        cudaFuncSetAttribute(gemm_hmma, cudaFuncAttributeMaxDynamicSharedMemorySize, GEMM_SMEM);
        attr_set = true;
    }

    gemm_hmma<<<NTOT/64, 256, GEMM_SMEM>>>(z, hw);
    build_w<<<BATCH*OC, 128>>>(bw);
    conv_mma<<<dim3(16, 2, BATCH), 512, CONV_SMEM>>>(x, out);
}